// round 3
// baseline (speedup 1.0000x reference)
#include <cuda_runtime.h>
#include <cuda_bf16.h>
#include <stdint.h>

#define Gx 106
#define G2x (106 * 106)
#define G3x (106 * 106 * 106)
#define MAXB 2
#define CROP 100
#define CROPV (100 * 100 * 100)

// Dual-parity scratch, float2 per slot = (grid_sum, acc_sum).
//   P0 region: slots [0, MAXB*G3x)            cell c -> slot c           (even c 16B-aligned)
//   P1 region: slots [MAXB*G3x, 2*MAXB*G3x+2) cell c -> slot SHIFT + c   (odd  c 16B-aligned)
#define SHIFT (MAXB * G3x + 1)
__device__ float2 g_combo2[2 * MAXB * G3x + 2];   // zero-initialized at module load

// ---------------------------------------------------------------------------
// Scatter: one thread per point. 4x4x4 window, exactly 32 red.v4 per point.
// Parity of the k window start selects the scratch copy -> always 16B aligned.
// ---------------------------------------------------------------------------
__global__ void __launch_bounds__(256)
splat_scatter_kernel(const float* __restrict__ points,
                     const float* __restrict__ dens,
                     const float* __restrict__ bbox,
                     int total, int Npb) {
    int t = blockIdx.x * blockDim.x + threadIdx.x;
    if (t >= total) return;

    int b = t / Npb;
    float d = __ldg(dens + t);

    float px = __ldg(points + 3 * t + 0);
    float py = __ldg(points + 3 * t + 1);
    float pz = __ldg(points + 3 * t + 2);

    int lo[3];
    float w[3][4];

    // Grid axis a uses point coordinate (2 - a) and bbox row (2 - a)
    // (the reference reverses the last dim of both points and bbox).
#pragma unroll
    for (int a = 0; a < 3; a++) {
        float c = (a == 0) ? pz : ((a == 1) ? py : px);
        int bd = 2 - a;
        float blo  = __fsub_rn(bbox[bd * 2 + 0], 0.03f);   // pad = (KR+1)*CELL
        float bhi  = __fadd_rn(bbox[bd * 2 + 1], 0.03f);
        float span = __fsub_rn(bhi, blo);
        // pg = ((c - blo) - CELL/2) / span * G   (op-for-op, IEEE rn)
        float tt = __fsub_rn(__fsub_rn(c, blo), 0.005f);
        float pg = __fmul_rn(__fdiv_rn(tt, span), 106.0f);
        float pgr = rintf(pg);           // round-half-even == jnp.round
        int   gi  = (int)pgr;
        float frac = pg - pgr;           // Sterbenz-exact

        // Only one of offsets -2/+2 is nonzero -> 4-wide window.
        int l = (frac < 0.0f) ? -2 : -1;
        lo[a] = gi + l;
#pragma unroll
        for (int o = 0; o < 4; o++) {
            float dd = (float)(l + o) - frac;            // exact
            w[a][o] = fmaxf(1.0f - fabsf(dd) * 0.5f, 0.0f);
        }
    }

    float w20 = w[2][0], w21 = w[2][1], w22 = w[2][2], w23 = w[2][3];

    int c0 = b * G3x + lo[0] * G2x + lo[1] * Gx + lo[2];  // window-start cell
    int sh = lo[2] & 1;                                    // parity -> copy select
    // G, G^2, G^3 even => parity(c0) == parity(lo[2]).
    float2* base = g_combo2 + ((size_t)c0 + (sh ? (size_t)SHIFT : (size_t)0));

#pragma unroll
    for (int i = 0; i < 4; i++) {
        float w0 = w[0][i];
#pragma unroll
        for (int j = 0; j < 4; j++) {
            float wij  = w0 * w[1][j];
            float wijd = wij * d;
            float2* p = base + i * G2x + j * Gx;

            asm volatile("red.global.add.v4.f32 [%0], {%1, %2, %3, %4};"
                         :: "l"(p),
                            "f"(wijd * w20), "f"(wij * w20),
                            "f"(wijd * w21), "f"(wij * w21)
                         : "memory");
            asm volatile("red.global.add.v4.f32 [%0], {%1, %2, %3, %4};"
                         :: "l"(p + 2),
                            "f"(wijd * w22), "f"(wij * w22),
                            "f"(wijd * w23), "f"(wij * w23)
                         : "memory");
        }
    }
}

// ---------------------------------------------------------------------------
// Finalize: sum P0+P1, re-zero both copies (restores the all-zero invariant
// for the next graph replay), normalize, crop [3 : G-4], write output.
// 2 cells per thread; covers the FULL G^3 extent (incl. out-of-crop edges).
// ---------------------------------------------------------------------------
__global__ void __launch_bounds__(256)
splat_finalize_kernel(float* __restrict__ out, int B, int writeAcc) {
    int q = blockIdx.x * blockDim.x + threadIdx.x;
    int half = (B * G3x) >> 1;
    if (q >= half) return;
    int c = q << 1;                       // even cell index

    float4 p0 = *reinterpret_cast<float4*>(g_combo2 + c);       // cells c, c+1 (P0)
    float2 p1a = g_combo2[SHIFT + c];                           // cell c   (P1)
    float2 p1b = g_combo2[SHIFT + c + 1];                       // cell c+1 (P1)

    // re-zero everything the scatter can have touched
    *reinterpret_cast<float4*>(g_combo2 + c) = make_float4(0.f, 0.f, 0.f, 0.f);
    g_combo2[SHIFT + c]     = make_float2(0.f, 0.f);
    g_combo2[SHIFT + c + 1] = make_float2(0.f, 0.f);

    float gv[2], av[2];
    gv[0] = p0.x + p1a.x;  av[0] = p0.y + p1a.y;
    gv[1] = p0.z + p1b.x;  av[1] = p0.w + p1b.y;

    int tot = B * CROPV;
#pragma unroll
    for (int u = 0; u < 2; u++) {
        int cc = c + u;
        int b = cc / G3x;
        int r = cc - b * G3x;
        int i = r / G2x;
        int rem = r - i * G2x;
        int j = rem / Gx;
        int k = rem - j * Gx;
        if (i >= 3 && i <= 102 && j >= 3 && j <= 102 && k >= 3 && k <= 102) {
            int o = b * CROPV + (i - 3) * (CROP * CROP) + (j - 3) * CROP + (k - 3);
            float a = av[u];
            float g = gv[u];
            out[o] = (a > 0.0f) ? (g / (a + 1e-9f)) : g;
            if (writeAcc) out[tot + o] = a;
        }
    }
}

// ---------------------------------------------------------------------------
extern "C" void kernel_launch(void* const* d_in, const int* in_sizes, int n_in,
                              void* d_out, int out_size) {
    const float* points = (const float*)d_in[0];
    const float* dens   = (const float*)d_in[1];
    const float* bbox   = (const float*)d_in[2];
    float* out = (float*)d_out;

    int total = in_sizes[1];              // B * N
    int B = total / 131072;               // fixed-shape problem: N = 131072
    if (B < 1) B = 1;
    if (B > MAXB) B = MAXB;
    int Npb = total / B;

    int writeAcc = (out_size >= 2 * B * CROPV) ? 1 : 0;

    // 1) scatter (scratch is all-zero: module-load init on run 1,
    //    finalize's re-zero on every subsequent run)
    {
        int tpb = 256;
        splat_scatter_kernel<<<(total + tpb - 1) / tpb, tpb>>>(points, dens, bbox,
                                                               total, Npb);
    }
    // 2) sum copies + re-zero + normalize + crop + write
    {
        int half = (B * G3x) >> 1;
        int tpb = 256;
        splat_finalize_kernel<<<(half + tpb - 1) / tpb, tpb>>>(out, B, writeAcc);
    }
}

// round 4
// speedup vs baseline: 1.3512x; 1.3512x over previous
#include <cuda_runtime.h>
#include <cuda_bf16.h>
#include <stdint.h>

#define Gx 106
#define G2x (106 * 106)
#define G3x (106 * 106 * 106)
#define MAXB 2
#define CROP 100
#define CROPV (100 * 100 * 100)

// Dual-parity scratch, float2 per slot = (grid_sum, acc_sum).
//   P0: cell c -> slot c            (even c 16B-aligned)
//   P1: cell c -> slot SHIFT + c    (odd  c 16B-aligned; SHIFT is odd)
#define SHIFT (MAXB * G3x + 1)
#define NSLOTS (2 * MAXB * G3x + 2)
__device__ float2 g_combo2[NSLOTS];   // zero at module load; re-zeroed per replay

// ---------------------------------------------------------------------------
// Zero the scratch. Runs first in every replay.
// ---------------------------------------------------------------------------
__global__ void __launch_bounds__(256)
splat_zero_kernel(int n4) {
    int i = blockIdx.x * blockDim.x + threadIdx.x;
    if (i < n4) {
        reinterpret_cast<float4*>(g_combo2)[i] = make_float4(0.f, 0.f, 0.f, 0.f);
    }
}

// ---------------------------------------------------------------------------
// Scatter: one thread per point. 4x4x4 window, exactly 32 red.v4 per point.
// Parity of the k window start selects the scratch copy -> always 16B aligned.
// (unchanged from round 3 — measured ~16us)
// ---------------------------------------------------------------------------
__global__ void __launch_bounds__(256)
splat_scatter_kernel(const float* __restrict__ points,
                     const float* __restrict__ dens,
                     const float* __restrict__ bbox,
                     int total, int Npb) {
    int t = blockIdx.x * blockDim.x + threadIdx.x;
    if (t >= total) return;

    int b = t / Npb;
    float d = __ldg(dens + t);

    float px = __ldg(points + 3 * t + 0);
    float py = __ldg(points + 3 * t + 1);
    float pz = __ldg(points + 3 * t + 2);

    int lo[3];
    float w[3][4];

    // Grid axis a uses point coordinate (2 - a) and bbox row (2 - a)
    // (the reference reverses the last dim of both points and bbox).
#pragma unroll
    for (int a = 0; a < 3; a++) {
        float c = (a == 0) ? pz : ((a == 1) ? py : px);
        int bd = 2 - a;
        float blo  = __fsub_rn(bbox[bd * 2 + 0], 0.03f);   // pad = (KR+1)*CELL
        float bhi  = __fadd_rn(bbox[bd * 2 + 1], 0.03f);
        float span = __fsub_rn(bhi, blo);
        // pg = ((c - blo) - CELL/2) / span * G   (op-for-op, IEEE rn)
        float tt = __fsub_rn(__fsub_rn(c, blo), 0.005f);
        float pg = __fmul_rn(__fdiv_rn(tt, span), 106.0f);
        float pgr = rintf(pg);           // round-half-even == jnp.round
        int   gi  = (int)pgr;
        float frac = pg - pgr;           // Sterbenz-exact

        // Only one of offsets -2/+2 is nonzero -> 4-wide window.
        int l = (frac < 0.0f) ? -2 : -1;
        lo[a] = gi + l;
#pragma unroll
        for (int o = 0; o < 4; o++) {
            float dd = (float)(l + o) - frac;            // exact
            w[a][o] = fmaxf(1.0f - fabsf(dd) * 0.5f, 0.0f);
        }
    }

    float w20 = w[2][0], w21 = w[2][1], w22 = w[2][2], w23 = w[2][3];

    int c0 = b * G3x + lo[0] * G2x + lo[1] * Gx + lo[2];  // window-start cell
    int sh = lo[2] & 1;                                    // parity -> copy select
    float2* base = g_combo2 + ((size_t)c0 + (sh ? (size_t)SHIFT : (size_t)0));

#pragma unroll
    for (int i = 0; i < 4; i++) {
        float w0 = w[0][i];
#pragma unroll
        for (int j = 0; j < 4; j++) {
            float wij  = w0 * w[1][j];
            float wijd = wij * d;
            float2* p = base + i * G2x + j * Gx;

            asm volatile("red.global.add.v4.f32 [%0], {%1, %2, %3, %4};"
                         :: "l"(p),
                            "f"(wijd * w20), "f"(wij * w20),
                            "f"(wijd * w21), "f"(wij * w21)
                         : "memory");
            asm volatile("red.global.add.v4.f32 [%0], {%1, %2, %3, %4};"
                         :: "l"(p + 2),
                            "f"(wijd * w22), "f"(wij * w22),
                            "f"(wijd * w23), "f"(wij * w23)
                         : "memory");
        }
    }
}

// ---------------------------------------------------------------------------
// Finalize: read-only over the CROP region. 4 k-cells per thread.
// P0+P1 sum, fast-divide normalize, coalesced float4 output stores.
// ---------------------------------------------------------------------------
__global__ void __launch_bounds__(256)
splat_finalize_kernel(float* __restrict__ out, int B, int writeAcc) {
    int q = blockIdx.x * blockDim.x + threadIdx.x;
    int tot = B * CROPV;
    int tot4 = tot >> 2;
    if (q >= tot4) return;
    int o = q << 2;

    // o -> (b, i, j, k) ; all divisors are compile-time constants
    int b = o / CROPV;
    int r = o - b * CROPV;
    int i = r / (CROP * CROP);
    int rem = r - i * (CROP * CROP);
    int j = rem / CROP;
    int k = rem - j * CROP;            // multiple of 4

    int src = b * G3x + (i + 3) * G2x + (j + 3) * Gx + (k + 3);
    const float2* __restrict__ p0 = g_combo2 + src;
    const float2* __restrict__ p1 = g_combo2 + SHIFT + src;

    float4 go, ao;
    float g0, a0;
#pragma unroll
    for (int u = 0; u < 4; u++) {
        float2 c0 = __ldg(p0 + u);
        float2 c1 = __ldg(p1 + u);
        float g = c0.x + c1.x;
        float a = c0.y + c1.y;
        float v = (a > 0.0f) ? __fdividef(g, a + 1e-9f) : g;
        if (u == 0) { go.x = v; ao.x = a; }
        if (u == 1) { go.y = v; ao.y = a; }
        if (u == 2) { go.z = v; ao.z = a; }
        if (u == 3) { go.w = v; ao.w = a; }
        (void)g0; (void)a0;
    }
    *reinterpret_cast<float4*>(out + o) = go;
    if (writeAcc) *reinterpret_cast<float4*>(out + tot + o) = ao;
}

// ---------------------------------------------------------------------------
extern "C" void kernel_launch(void* const* d_in, const int* in_sizes, int n_in,
                              void* d_out, int out_size) {
    const float* points = (const float*)d_in[0];
    const float* dens   = (const float*)d_in[1];
    const float* bbox   = (const float*)d_in[2];
    float* out = (float*)d_out;

    int total = in_sizes[1];              // B * N
    int B = total / 131072;               // fixed-shape problem: N = 131072
    if (B < 1) B = 1;
    if (B > MAXB) B = MAXB;
    int Npb = total / B;

    int writeAcc = (out_size >= 2 * B * CROPV) ? 1 : 0;

    // 1) zero scratch (idempotent on first replay; restores invariant after)
    {
        int n4 = NSLOTS / 2;              // float4 count
        int tpb = 256;
        splat_zero_kernel<<<(n4 + tpb - 1) / tpb, tpb>>>(n4);
    }
    // 2) scatter
    {
        int tpb = 256;
        splat_scatter_kernel<<<(total + tpb - 1) / tpb, tpb>>>(points, dens, bbox,
                                                               total, Npb);
    }
    // 3) normalize + crop + write (read-only w.r.t. scratch)
    {
        int tot4 = (B * CROPV) >> 2;
        int tpb = 256;
        splat_finalize_kernel<<<(tot4 + tpb - 1) / tpb, tpb>>>(out, B, writeAcc);
    }
}